// round 9
// baseline (speedup 1.0000x reference)
#include <cuda_runtime.h>
#include <cuda_fp16.h>
#include <cstddef>

// SumLayer: out[nids[n], :] = log( sum_e params[pids[n,e]] * exp(element_mars[cids[n,e], :]) )
// N=32768, E=32, B=256, element_mars [65536, 256] fp32.
//
// v6: two column chunks of 128, pipelined:
//   exp0 | mix(exp1 ‖ gather0) | gather1
// Gather uses HALF-WARP per node (16 lanes x 16B = 128 cols) so per-byte
// instruction cost matches the proven full-width gather (LDG.128 lanes).
// Exp uses 16 floats/thread (4 front-batched float4 loads, MLP=4).

constexpr int E         = 32;
constexpr int B         = 256;
constexpr int ROWS      = 65536;
constexpr int HALF_COLS = 128;
constexpr int NPC       = 16;        // nodes per CTA (half-warp per node)

union Vec8h { uint4 u; __half2 h[4]; };

// fp16 scratch: exp(element_mars), row-major [ROWS][B] halves = 33.5 MB.
__device__ uint4 g_exp[(size_t)ROWS * B / 8];

// ---- exp for one 128-col chunk: thread handles 16 consecutive floats ----
__device__ __forceinline__ void exp_chunk(const float* __restrict__ em,
                                          int chunk, int cta, int tid)
{
    const int t    = cta * 256 + tid;      // 0 .. ROWS*8-1
    const int row  = t >> 3;
    const int slot = t & 7;                // 8 x 16-float slots per chunk-row
    if (row >= ROWS) return;

    const float4* src = reinterpret_cast<const float4*>(em)
                      + (size_t)row * (B / 4) + chunk * (HALF_COLS / 4) + slot * 4;
    // 4 independent loads, front-batched for MLP
    const float4 v0 = src[0];
    const float4 v1 = src[1];
    const float4 v2 = src[2];
    const float4 v3 = src[3];

    Vec8h r0, r1;
    r0.h[0] = __floats2half2_rn(__expf(v0.x), __expf(v0.y));
    r0.h[1] = __floats2half2_rn(__expf(v0.z), __expf(v0.w));
    r0.h[2] = __floats2half2_rn(__expf(v1.x), __expf(v1.y));
    r0.h[3] = __floats2half2_rn(__expf(v1.z), __expf(v1.w));
    r1.h[0] = __floats2half2_rn(__expf(v2.x), __expf(v2.y));
    r1.h[1] = __floats2half2_rn(__expf(v2.z), __expf(v2.w));
    r1.h[2] = __floats2half2_rn(__expf(v3.x), __expf(v3.y));
    r1.h[3] = __floats2half2_rn(__expf(v3.z), __expf(v3.w));

    uint4* dst = g_exp + (size_t)row * (B / 8) + chunk * (HALF_COLS / 8) + slot * 2;
    dst[0] = r0.u;
    dst[1] = r1.u;
}

// ---- gather for one 128-col chunk: half-warp per node, 16B per lane ----
__device__ __forceinline__ void gather_chunk(
    const float* __restrict__ params,
    const int*   __restrict__ nids,
    const int*   __restrict__ cids,
    const int*   __restrict__ pids,
    float*       __restrict__ out,
    int n_nodes, int chunk, int node_base, int tid)
{
    __shared__ int2 s_cw[NPC][E];          // {cid, weight bits}

    // Stage 16 nodes x 32 edges = 512 pairs with 256 threads (2 each).
#pragma unroll
    for (int k = 0; k < 2; ++k) {
        const int j  = tid + k * 256;
        const int nn = node_base + (j >> 5);
        if (nn < n_nodes) {
            const size_t idx = (size_t)nn * E + (j & 31);
            s_cw[j >> 5][j & 31] =
                make_int2(cids[idx], __float_as_int(__ldg(params + pids[idx])));
        }
    }
    __syncthreads();

    const int hw     = tid >> 4;           // half-warp = node (0..15)
    const int lane16 = tid & 15;           // lane within node, owns 8 cols
    const int n      = node_base + hw;
    if (n >= n_nodes) return;

    // Full row = B/8 = 32 uint4; chunk covers 16; lane16 owns one (16B).
    const uint4* base = g_exp + chunk * (HALF_COLS / 8) + lane16;

    float a0 = 0.f, a1 = 0.f, a2 = 0.f, a3 = 0.f,
          a4 = 0.f, a5 = 0.f, a6 = 0.f, a7 = 0.f;

#pragma unroll
    for (int e = 0; e < E; ++e) {
        const int2  cw = s_cw[hw][e];      // uniform per half-warp
        const float w  = __int_as_float(cw.y);
        Vec8h v;
        v.u = base[(size_t)cw.x * (B / 8)];
        const float2 f0 = __half22float2(v.h[0]);
        const float2 f1 = __half22float2(v.h[1]);
        const float2 f2 = __half22float2(v.h[2]);
        const float2 f3 = __half22float2(v.h[3]);
        a0 = fmaf(w, f0.x, a0);  a1 = fmaf(w, f0.y, a1);
        a2 = fmaf(w, f1.x, a2);  a3 = fmaf(w, f1.y, a3);
        a4 = fmaf(w, f2.x, a4);  a5 = fmaf(w, f2.y, a5);
        a6 = fmaf(w, f3.x, a6);  a7 = fmaf(w, f3.y, a7);
    }

    const int nid = nids[n];
    float* orow = out + (size_t)nid * B + chunk * HALF_COLS + lane16 * 8;
    float4 o0, o1;
    o0.x = __logf(fmaxf(a0, 1e-10f));
    o0.y = __logf(fmaxf(a1, 1e-10f));
    o0.z = __logf(fmaxf(a2, 1e-10f));
    o0.w = __logf(fmaxf(a3, 1e-10f));
    o1.x = __logf(fmaxf(a4, 1e-10f));
    o1.y = __logf(fmaxf(a5, 1e-10f));
    o1.z = __logf(fmaxf(a6, 1e-10f));
    o1.w = __logf(fmaxf(a7, 1e-10f));
    *reinterpret_cast<float4*>(orow)     = o0;
    *reinterpret_cast<float4*>(orow + 4) = o1;
}

// ---------------- kernels ----------------
__global__ __launch_bounds__(256, 8) void exp0_kernel(const float* __restrict__ em)
{
    exp_chunk(em, 0, blockIdx.x, threadIdx.x);
}

// exp1 (DRAM-bound) interleaved 1:1 with gather0 (L2-bound).
__global__ __launch_bounds__(256, 8) void mix_kernel(
    const float* __restrict__ em,
    const float* __restrict__ params,
    const int*   __restrict__ nids,
    const int*   __restrict__ cids,
    const int*   __restrict__ pids,
    float*       __restrict__ out,
    int n_nodes)
{
    if (blockIdx.x & 1)
        exp_chunk(em, 1, blockIdx.x >> 1, threadIdx.x);
    else
        gather_chunk(params, nids, cids, pids, out, n_nodes, 0,
                     (blockIdx.x >> 1) * NPC, threadIdx.x);
}

__global__ __launch_bounds__(256, 8) void gather1_kernel(
    const float* __restrict__ params,
    const int*   __restrict__ nids,
    const int*   __restrict__ cids,
    const int*   __restrict__ pids,
    float*       __restrict__ out,
    int n_nodes)
{
    gather_chunk(params, nids, cids, pids, out, n_nodes, 1,
                 blockIdx.x * NPC, threadIdx.x);
}

extern "C" void kernel_launch(void* const* d_in, const int* in_sizes, int n_in,
                              void* d_out, int out_size)
{
    const float* element_mars = (const float*)d_in[1];
    const float* params       = (const float*)d_in[2];
    const int*   nids         = (const int*)d_in[3];
    const int*   cids         = (const int*)d_in[4];
    const int*   pids         = (const int*)d_in[5];
    float*       out          = (float*)d_out;

    const int N       = in_sizes[3];
    const int expCTAs = (ROWS * 8 + 255) / 256;        // 2048 per chunk
    const int gCTAs   = (N + NPC - 1) / NPC;           // 2048 per chunk
    const int mixCTAs = 2 * (expCTAs > gCTAs ? expCTAs : gCTAs);

    exp0_kernel<<<expCTAs, 256>>>(element_mars);

    mix_kernel<<<mixCTAs, 256>>>(element_mars, params, nids, cids, pids,
                                 out, N);

    gather1_kernel<<<gCTAs, 256>>>(params, nids, cids, pids, out, N);
}

// round 10
// speedup vs baseline: 1.2283x; 1.2283x over previous
#include <cuda_runtime.h>
#include <cuda_fp16.h>
#include <cstddef>

// SumLayer: out[nids[n], :] = log( sum_e params[pids[n,e]] * exp(element_mars[cids[n,e], :]) )
// N=32768, E=32, B=256, element_mars [65536, 256] fp32.
//
// v7: revert to serial two-pass (overlap can't help: DRAM traffic also
// transits the path-independent LTS cap, so exp+gather share one ceiling).
//   Pass 1: exp(element_mars) -> fp16 scratch, __ldcs streaming reads.
//   Pass 2: persistent warp-per-node gather (grid = 148*8 CTAs, warp-granular
//           work distribution to kill the tail wave), 16B/lane LDG, FFMA loop.

constexpr int E     = 32;
constexpr int B     = 256;
constexpr int ROWS  = 65536;
constexpr int WPC   = 8;             // warps per CTA

union Vec8h { uint4 u; __half2 h[4]; };

// fp16 scratch: exp(element_mars), ROWS x B halves = 33.5 MB (L2-resident).
__device__ uint4 g_exp[(size_t)ROWS * B / 8];

// ---------------- Pass 1: elementwise exp, fp32 -> fp16 ----------------
// Thread handles 8 floats (2 x float4, streaming loads) -> one uint4.
__global__ __launch_bounds__(256) void exp_kernel(
    const float4* __restrict__ in, int n8)
{
    const int i = blockIdx.x * blockDim.x + threadIdx.x;
    if (i >= n8) return;
    const float4 v0 = __ldcs(in + i * 2);
    const float4 v1 = __ldcs(in + i * 2 + 1);
    Vec8h r;
    r.h[0] = __floats2half2_rn(__expf(v0.x), __expf(v0.y));
    r.h[1] = __floats2half2_rn(__expf(v0.z), __expf(v0.w));
    r.h[2] = __floats2half2_rn(__expf(v1.x), __expf(v1.y));
    r.h[3] = __floats2half2_rn(__expf(v1.z), __expf(v1.w));
    g_exp[i] = r.u;
}

// ---------------- Pass 2: weighted gather-sum + log ----------------
// Persistent: each warp strides over nodes; warp-private smem staging.
__global__ __launch_bounds__(32 * WPC, 8) void gather_kernel(
    const float* __restrict__ params,
    const int*   __restrict__ nids,
    const int*   __restrict__ cids,
    const int*   __restrict__ pids,
    float*       __restrict__ out,
    int          n_nodes)
{
    __shared__ int2 s_cw[WPC][E];        // {cid, weight-bits}, warp-private row

    const int tid    = threadIdx.x;
    const int lane   = tid & 31;
    const int wlocal = tid >> 5;
    const int gw     = blockIdx.x * WPC + wlocal;   // global warp id
    const int nw     = gridDim.x * WPC;             // total warps

    // Lane-fixed base: row occupies B/8 = 32 uint4s; lane owns one (16B).
    const uint4* base = g_exp + lane;

    for (int n = gw; n < n_nodes; n += nw) {
        const size_t idx = (size_t)n * E + lane;     // one edge per lane
        s_cw[wlocal][lane] = make_int2(cids[idx],
                                       __float_as_int(__ldg(params + pids[idx])));
        __syncwarp();

        float a0 = 0.f, a1 = 0.f, a2 = 0.f, a3 = 0.f,
              a4 = 0.f, a5 = 0.f, a6 = 0.f, a7 = 0.f;

#pragma unroll
        for (int e = 0; e < E; ++e) {
            const int2  cw = s_cw[wlocal][e];        // warp-uniform LDS.64
            const float w  = __int_as_float(cw.y);
            Vec8h v;
            v.u = base[(size_t)cw.x * (B / 8)];
            const float2 f0 = __half22float2(v.h[0]);
            const float2 f1 = __half22float2(v.h[1]);
            const float2 f2 = __half22float2(v.h[2]);
            const float2 f3 = __half22float2(v.h[3]);
            a0 = fmaf(w, f0.x, a0);  a1 = fmaf(w, f0.y, a1);
            a2 = fmaf(w, f1.x, a2);  a3 = fmaf(w, f1.y, a3);
            a4 = fmaf(w, f2.x, a4);  a5 = fmaf(w, f2.y, a5);
            a6 = fmaf(w, f3.x, a6);  a7 = fmaf(w, f3.y, a7);
        }

        const int nid = nids[n];                     // warp-uniform broadcast
        float* orow = out + (size_t)nid * B + lane * 8;
        float4 o0, o1;
        o0.x = __logf(fmaxf(a0, 1e-10f));
        o0.y = __logf(fmaxf(a1, 1e-10f));
        o0.z = __logf(fmaxf(a2, 1e-10f));
        o0.w = __logf(fmaxf(a3, 1e-10f));
        o1.x = __logf(fmaxf(a4, 1e-10f));
        o1.y = __logf(fmaxf(a5, 1e-10f));
        o1.z = __logf(fmaxf(a6, 1e-10f));
        o1.w = __logf(fmaxf(a7, 1e-10f));
        *reinterpret_cast<float4*>(orow)     = o0;
        *reinterpret_cast<float4*>(orow + 4) = o1;

        __syncwarp();    // staging row is reused next iteration
    }
}

extern "C" void kernel_launch(void* const* d_in, const int* in_sizes, int n_in,
                              void* d_out, int out_size)
{
    const float* element_mars = (const float*)d_in[1];
    const float* params       = (const float*)d_in[2];
    const int*   nids         = (const int*)d_in[3];
    const int*   cids         = (const int*)d_in[4];
    const int*   pids         = (const int*)d_in[5];
    float*       out          = (float*)d_out;

    const int N     = in_sizes[3];           // nodes
    const int n_els = in_sizes[1];           // ROWS * B
    const int n8    = n_els / 8;

    exp_kernel<<<(n8 + 255) / 256, 256>>>((const float4*)element_mars, n8);

    // Persistent gather: 8 CTAs per SM on 148 SMs.
    gather_kernel<<<148 * 8, 32 * WPC>>>(params, nids, cids, pids, out, N);
}

// round 12
// speedup vs baseline: 1.2724x; 1.0359x over previous
#include <cuda_runtime.h>
#include <cuda_fp16.h>
#include <cstddef>

// SumLayer: out[nids[n], :] = log( sum_e params[pids[n,e]] * exp(element_mars[cids[n,e], :]) )
// N=32768, E=32, B=256, element_mars [65536, 256] fp32.
//
// v8 (verbatim resubmit after transient container failure):
//   Pass 1 (v7): exp(element_mars) -> fp16 scratch, __ldcs streaming reads.
//                ~10 us, at its DRAM-read floor.
//   Pass 2 (v4): wave-launched gather, 8 nodes per 256-thr CTA, one warp per
//                node, 16B/lane LDG from L2-resident scratch, FFMA loop.
//                ~39 us, at the ~15 TB/s LTS cap.

constexpr int E    = 32;
constexpr int B    = 256;
constexpr int ROWS = 65536;
constexpr int NPC  = 8;              // nodes per CTA (1 warp per node)

union Vec8h { uint4 u; __half2 h[4]; };

// fp16 scratch: exp(element_mars), ROWS x B halves = 33.5 MB (L2-resident).
__device__ uint4 g_exp[(size_t)ROWS * B / 8];

// ---------------- Pass 1: elementwise exp, fp32 -> fp16 ----------------
__global__ __launch_bounds__(256) void exp_kernel(
    const float4* __restrict__ in, int n8)
{
    const int i = blockIdx.x * blockDim.x + threadIdx.x;
    if (i >= n8) return;
    const float4 v0 = __ldcs(in + i * 2);
    const float4 v1 = __ldcs(in + i * 2 + 1);
    Vec8h r;
    r.h[0] = __floats2half2_rn(__expf(v0.x), __expf(v0.y));
    r.h[1] = __floats2half2_rn(__expf(v0.z), __expf(v0.w));
    r.h[2] = __floats2half2_rn(__expf(v1.x), __expf(v1.y));
    r.h[3] = __floats2half2_rn(__expf(v1.z), __expf(v1.w));
    g_exp[i] = r.u;
}

// ---------------- Pass 2: weighted gather-sum + log ----------------
__global__ __launch_bounds__(32 * NPC, 8) void gather_kernel(
    const float* __restrict__ params,
    const int*   __restrict__ nids,
    const int*   __restrict__ cids,
    const int*   __restrict__ pids,
    float*       __restrict__ out,
    int          n_nodes)
{
    __shared__ int2 s_cw[NPC][E];        // {cid, weight-bits}

    const int tid  = threadIdx.x;
    const int ln   = tid >> 5;           // warp = node within CTA
    const int lane = tid & 31;
    const int n    = blockIdx.x * NPC + ln;

    if (n < n_nodes) {
        const size_t idx = (size_t)n * E + lane;     // one edge per lane
        s_cw[ln][lane] = make_int2(cids[idx],
                                   __float_as_int(__ldg(params + pids[idx])));
    }
    __syncwarp();                        // staging is warp-private
    if (n >= n_nodes) return;

    // Lane-fixed base: row occupies B/8 = 32 uint4s; lane owns one (16B).
    const uint4* base = g_exp + lane;

    float a0 = 0.f, a1 = 0.f, a2 = 0.f, a3 = 0.f,
          a4 = 0.f, a5 = 0.f, a6 = 0.f, a7 = 0.f;

#pragma unroll
    for (int e = 0; e < E; ++e) {
        const int2  cw = s_cw[ln][e];    // warp-uniform LDS.64 broadcast
        const float w  = __int_as_float(cw.y);
        Vec8h v;
        v.u = base[(size_t)cw.x * (B / 8)];
        const float2 f0 = __half22float2(v.h[0]);
        const float2 f1 = __half22float2(v.h[1]);
        const float2 f2 = __half22float2(v.h[2]);
        const float2 f3 = __half22float2(v.h[3]);
        a0 = fmaf(w, f0.x, a0);  a1 = fmaf(w, f0.y, a1);
        a2 = fmaf(w, f1.x, a2);  a3 = fmaf(w, f1.y, a3);
        a4 = fmaf(w, f2.x, a4);  a5 = fmaf(w, f2.y, a5);
        a6 = fmaf(w, f3.x, a6);  a7 = fmaf(w, f3.y, a7);
    }

    const int nid = nids[n];             // warp-uniform broadcast
    float* orow = out + (size_t)nid * B + lane * 8;
    float4 o0, o1;
    o0.x = __logf(fmaxf(a0, 1e-10f));
    o0.y = __logf(fmaxf(a1, 1e-10f));
    o0.z = __logf(fmaxf(a2, 1e-10f));
    o0.w = __logf(fmaxf(a3, 1e-10f));
    o1.x = __logf(fmaxf(a4, 1e-10f));
    o1.y = __logf(fmaxf(a5, 1e-10f));
    o1.z = __logf(fmaxf(a6, 1e-10f));
    o1.w = __logf(fmaxf(a7, 1e-10f));
    *reinterpret_cast<float4*>(orow)     = o0;
    *reinterpret_cast<float4*>(orow + 4) = o1;
}

extern "C" void kernel_launch(void* const* d_in, const int* in_sizes, int n_in,
                              void* d_out, int out_size)
{
    const float* element_mars = (const float*)d_in[1];
    const float* params       = (const float*)d_in[2];
    const int*   nids         = (const int*)d_in[3];
    const int*   cids         = (const int*)d_in[4];
    const int*   pids         = (const int*)d_in[5];
    float*       out          = (float*)d_out;

    const int N     = in_sizes[3];           // nodes
    const int n_els = in_sizes[1];           // ROWS * B
    const int n8    = n_els / 8;

    exp_kernel<<<(n8 + 255) / 256, 256>>>((const float4*)element_mars, n8);

    gather_kernel<<<(N + NPC - 1) / NPC, 32 * NPC>>>(
        params, nids, cids, pids, out, N);
}